// round 7
// baseline (speedup 1.0000x reference)
#include <cuda_runtime.h>
#include <cuda_bf16.h>

// Problem constants
#define NN    1024
#define II    64
#define RTAIL 960          // N - I
#define TAILK 896          // rows 128..1023
#define NWARM 25
#define CB    16           // warm cluster size
#define NCLUST 8           // clusters in kernel1
#define NCTA  (CB * NCLUST)   // 128 CTAs total
#define NWORK (NCTA - CB)     // 112 gemm workers
#define JB    60           // tail columns per warm block (16*60 = 960)
#define BROWS 16384
#define TM    128          // gemm rows per tile

// ---------------- device scratch (static: no allocations allowed) -------------
__device__ float d_C[1024];                    // per-column constant (zeros pad)
__device__ float d_P[BROWS * 1024];            // raw A@W product (67MB, L2-res)

// ---------------- helpers ----------------------------------------------------
static __device__ __forceinline__ float sigd(float idv, float e, float iv, float b) {
    return expf(-b * fabsf(e - idv)) - expf(-b * fabsf(iv - idv));
}
static __device__ __forceinline__ unsigned long long splat2(float x) {
    unsigned long long d;
    asm("mov.b64 %0, {%1, %1};" : "=l"(d) : "f"(x));
    return d;
}
static __device__ __forceinline__ unsigned long long ffma2(unsigned long long a,
                                                           unsigned long long b,
                                                           unsigned long long c) {
    unsigned long long d;
    asm("fma.rn.f32x2 %0, %1, %2, %3;" : "=l"(d) : "l"(a), "l"(b), "l"(c));
    return d;
}
static __device__ __forceinline__ void unpack2(unsigned long long v, float& lo, float& hi) {
    asm("mov.b64 {%0, %1}, %2;" : "=f"(lo), "=f"(hi) : "l"(v));
}
static __device__ __forceinline__ float warp_sum(float v) {
    #pragma unroll
    for (int o = 16; o; o >>= 1) v += __shfl_xor_sync(0xffffffffu, v, o);
    return v;
}
static __device__ __forceinline__ unsigned smem_u32(const void* p) {
    unsigned a;
    asm("{ .reg .u64 t; cvta.to.shared.u64 t, %1; cvt.u32.u64 %0, t; }"
        : "=r"(a) : "l"(p));
    return a;
}
static __device__ __forceinline__ void cluster_sync_hw() {
    asm volatile("barrier.cluster.arrive.aligned;" ::: "memory");
    asm volatile("barrier.cluster.wait.aligned;"   ::: "memory");
}
static __device__ __forceinline__ float dsmem_ld(unsigned local_addr, int rank) {
    unsigned rem;
    asm("mapa.shared::cluster.u32 %0, %1, %2;" : "=r"(rem) : "r"(local_addr), "r"(rank));
    float v;
    asm volatile("ld.shared::cluster.f32 %0, [%1];" : "=f"(v) : "r"(rem));
    return v;
}

// ---------------- warm smem layout (floats) -----------------------------------
#define OFF_U   (JB * TAILK)          // u_s[960]
#define OFF_H   (OFF_U + RTAIL)       // h_s[60] (+pad)
#define OFF_XB  (OFF_H + 64)          // xbuf[2][60]
#define OFF_RED (OFF_XB + 2 * JB)     // red[8]
#define WARM_FLOATS (OFF_RED + 8)
#define K1_SMEM (WARM_FLOATS * 4)     // 219,648 B (>= gemm worker needs)

// gemm worker layout (within same dynamic smem)
#define AS_STRIDE 132

// ---------------- kernel 1: warm cluster + independent gemm workers ----------
__global__ void __launch_bounds__(256, 1) __cluster_dims__(CB, 1, 1)
fused_kernel(const float* __restrict__ inp, const float* __restrict__ ids,
             const float* __restrict__ enh, const float* __restrict__ inh,
             const float* __restrict__ beta, const float* __restrict__ delta) {
    extern __shared__ float sm[];
    const float b  = beta[0];
    const float dn = delta[0] * (1.0f / (float)NN);
    const int tid  = threadIdx.x;
    const int bid  = blockIdx.x;
    const int warp = tid >> 5;
    const int lane = tid & 31;

    if (bid < CB) {
        // ================== WARM ROLE (cluster 0) ============================
        float* w_s = sm;              // [60][896]
        float* u_s = sm + OFF_U;      // [960]
        float* h_s = sm + OFF_H;      // [60]
        float* xb  = sm + OFF_XB;     // [2][60]
        float* red = sm + OFF_RED;    // [8]
        const int j0 = bid * JB;

        for (int idx = tid; idx < JB * TAILK; idx += 256) {
            int c = idx / TAILK, i = idx - c * TAILK;
            w_s[idx] = sigd(ids[II + j0 + c], enh[128 + i], inh[128 + i], b);
        }
        for (int c = warp; c < JB; c += 8) {
            float idv = ids[II + j0 + c];
            float hv = sigd(idv, enh[lane], inh[lane], b)
                     + sigd(idv, enh[lane + 32], inh[lane + 32], b);
            hv = warp_sum(hv);
            if (lane == 0) h_s[c] = hv * (1.0f / (float)NN);
        }
        for (int i = tid; i < RTAIL; i += 256) u_s[i] = 1.0f / (float)NN;
        if (bid == 0 && tid < 64) d_C[RTAIL + tid] = 0.f;
        __syncthreads();

        const int nc = (warp < 4) ? 8 : 7;
        const int cbse = (warp < 4) ? warp * 8 : 32 + (warp - 4) * 7;
        const float* wp = &w_s[cbse * TAILK];

        float inv = 1.0f;
        for (int it = 0; it < NWARM; ++it) {
            const int buf = it & 1;
            float acc[8];
            #pragma unroll
            for (int c = 0; c < 8; ++c) acc[c] = 0.f;
            #pragma unroll 4
            for (int q = 0; q < 28; ++q) {
                const int off = lane + 32 * q;
                float u = u_s[64 + off];
                #pragma unroll
                for (int c = 0; c < 8; ++c)
                    acc[c] = fmaf(u, wp[c * TAILK + off], acc[c]);
            }
            #pragma unroll
            for (int c = 0; c < 8; ++c) {
                float dsum = warp_sum(acc[c]);
                if (lane == 0 && c < nc) {
                    int cl = cbse + c;
                    float uo = u_s[j0 + cl];
                    float nv = fmaxf(uo * inv + dn * (h_s[cl] + dsum * inv), 0.f);
                    xb[buf * JB + cl] = nv;
                }
            }
            cluster_sync_hw();

            float p = 0.f;
            const unsigned xb_base = smem_u32(&xb[buf * JB]);
            #pragma unroll
            for (int r = 0; r < 4; ++r) {
                int i = tid + 256 * r;
                if (i < RTAIL) {
                    int owner = i / JB;
                    int slot  = i - owner * JB;
                    float v = dsmem_ld(xb_base + slot * 4, owner);
                    u_s[i] = v;
                    p += v;
                }
            }
            p = warp_sum(p);
            if (lane == 0) red[warp] = p;
            __syncthreads();
            float s = red[0] + red[1] + red[2] + red[3]
                    + red[4] + red[5] + red[6] + red[7];
            inv = (s > 0.f) ? 1.0f / s : 1.0f;
        }

        // final: C_j = u_j*inv + dn*dot(u)*inv (head term comes from GEMM)
        {
            float acc[8];
            #pragma unroll
            for (int c = 0; c < 8; ++c) acc[c] = 0.f;
            #pragma unroll 4
            for (int q = 0; q < 28; ++q) {
                const int off = lane + 32 * q;
                float u = u_s[64 + off];
                #pragma unroll
                for (int c = 0; c < 8; ++c)
                    acc[c] = fmaf(u, wp[c * TAILK + off], acc[c]);
            }
            #pragma unroll
            for (int c = 0; c < 8; ++c) {
                float dsum = warp_sum(acc[c]);
                if (lane == 0 && c < nc) {
                    int cl = cbse + c;
                    d_C[j0 + cl] = u_s[j0 + cl] * inv + dn * dsum * inv;
                }
            }
        }
        cluster_sync_hw();   // peers may still DSMEM-read
    } else {
        // ================== GEMM WORKER ROLE =================================
        float* As = sm;                      // [64][132]  A^T: As[k][row]
        float* Ws = As + 64 * AS_STRIDE;     // [64][132]  own W chunk

        const int w = bid - CB;              // 0..111
        const int chunk = w & 7;             // 8 chunks of 128 cols
        const int wc = w >> 3;               // 0..13 row-tile lane
        const int cbase = chunk * 128;
        const int tx = tid & 15, ty = tid >> 4;

        // build my W chunk once: Ws[k][j] = dn*sigd(ids[64+cbase+j], ...)
        for (int idx = tid; idx < 64 * 128; idx += 256) {
            int k = idx >> 7, j = idx & 127;
            int col = cbase + j;
            float v = 0.f;
            if (col < RTAIL) v = dn * sigd(ids[II + col], enh[k], inh[k], b);
            Ws[k * AS_STRIDE + j] = v;
        }

        for (int rt = wc; rt < BROWS / TM; rt += (NWORK >> 3)) {
            const int b0 = rt * TM;
            __syncthreads();   // protect As reuse across tiles
            for (int idx = tid; idx < TM * 64; idx += 256) {
                int row = idx >> 6, k = idx & 63;
                As[k * AS_STRIDE + row] = inp[(b0 + row) * 64 + k];
            }
            __syncthreads();

            unsigned long long acc[8][4];
            #pragma unroll
            for (int r = 0; r < 8; ++r)
                #pragma unroll
                for (int c = 0; c < 4; ++c) acc[r][c] = 0ull;

            #pragma unroll 4
            for (int k = 0; k < 64; ++k) {
                float4 a0 = *(const float4*)&As[k * AS_STRIDE + ty * 8];
                float4 a1 = *(const float4*)&As[k * AS_STRIDE + ty * 8 + 4];
                ulonglong2 w01 = *(const ulonglong2*)&Ws[k * AS_STRIDE + tx * 8];
                ulonglong2 w23 = *(const ulonglong2*)&Ws[k * AS_STRIDE + tx * 8 + 4];
                unsigned long long sp[8];
                sp[0] = splat2(a0.x); sp[1] = splat2(a0.y);
                sp[2] = splat2(a0.z); sp[3] = splat2(a0.w);
                sp[4] = splat2(a1.x); sp[5] = splat2(a1.y);
                sp[6] = splat2(a1.z); sp[7] = splat2(a1.w);
                #pragma unroll
                for (int r = 0; r < 8; ++r) {
                    acc[r][0] = ffma2(sp[r], w01.x, acc[r][0]);
                    acc[r][1] = ffma2(sp[r], w01.y, acc[r][1]);
                    acc[r][2] = ffma2(sp[r], w23.x, acc[r][2]);
                    acc[r][3] = ffma2(sp[r], w23.y, acc[r][3]);
                }
            }

            // store raw P tile (row stride 1024)
            #pragma unroll
            for (int r = 0; r < 8; ++r) {
                int row = b0 + ty * 8 + r;
                float4 v0, v1;
                unpack2(acc[r][0], v0.x, v0.y);
                unpack2(acc[r][1], v0.z, v0.w);
                unpack2(acc[r][2], v1.x, v1.y);
                unpack2(acc[r][3], v1.z, v1.w);
                float4* dst = (float4*)&d_P[row * 1024 + cbase + tx * 8];
                dst[0] = v0;
                dst[1] = v1;
            }
        }
    }
}

// ---------------- kernel 2: epilogue (C + relu + rowsum + normalize) ---------
// 256 CTAs x 256 threads, 64 rows per CTA, 8 rows per warp.
__global__ void __launch_bounds__(256)
epi_kernel(float* __restrict__ out) {
    const int tid  = threadIdx.x;
    const int warp = tid >> 5;
    const int lane = tid & 31;
    const int r0   = blockIdx.x * 64 + warp * 8;

    // preload C for my column lanes: cols lane*4 + 128*q
    float4 cv[8];
    #pragma unroll
    for (int q = 0; q < 8; ++q)
        cv[q] = *(const float4*)&d_C[lane * 4 + 128 * q];

    #pragma unroll
    for (int r = 0; r < 8; ++r) {
        const int row = r0 + r;
        const float* Pr = &d_P[row * 1024];
        float4 keep;            // relu'd cols lane*4..+3 (q==0), lanes 0..15
        float s = 0.f;
        #pragma unroll
        for (int q = 0; q < 8; ++q) {
            float4 p = *(const float4*)&Pr[lane * 4 + 128 * q];
            float4 v;
            v.x = fmaxf(p.x + cv[q].x, 0.f);
            v.y = fmaxf(p.y + cv[q].y, 0.f);
            v.z = fmaxf(p.z + cv[q].z, 0.f);
            v.w = fmaxf(p.w + cv[q].w, 0.f);
            s += (v.x + v.y) + (v.z + v.w);
            if (q == 0) keep = v;
        }
        s = warp_sum(s);
        float inv = (s > 0.f) ? 1.0f / s : 1.0f;
        if (lane < 16) {
            float4 o;
            o.x = keep.x * inv; o.y = keep.y * inv;
            o.z = keep.z * inv; o.w = keep.w * inv;
            *(float4*)&out[row * 64 + lane * 4] = o;
        }
    }
}

// ---------------- launch ------------------------------------------------------
extern "C" void kernel_launch(void* const* d_in, const int* in_sizes, int n_in,
                              void* d_out, int out_size) {
    const float* inputs = (const float*)d_in[0];
    const float* ids    = (const float*)d_in[1];
    const float* enh    = (const float*)d_in[2];
    const float* inh    = (const float*)d_in[3];
    const float* beta   = (const float*)d_in[4];
    const float* delta  = (const float*)d_in[5];

    cudaFuncSetAttribute(fused_kernel,
                         cudaFuncAttributeNonPortableClusterSizeAllowed, 1);
    cudaFuncSetAttribute(fused_kernel,
                         cudaFuncAttributeMaxDynamicSharedMemorySize, K1_SMEM);

    fused_kernel<<<NCTA, 256, K1_SMEM>>>(inputs, ids, enh, inh, beta, delta);
    epi_kernel<<<BROWS / 64, 256>>>((float*)d_out);
}

// round 8
// speedup vs baseline: 1.3662x; 1.3662x over previous
#include <cuda_runtime.h>
#include <cuda_bf16.h>

// Problem constants
#define NN    1024
#define II    64
#define RTAIL 960          // N - I
#define TAILK 896          // rows 128..1023
#define TAILP 448          // TAILK/2 (bf16x2 pairs)
#define NWARM 25
#define CB    16           // warm cluster size == grid size
#define JB    60           // tail columns per warm block (16*60 = 960)
#define BROWS 16384

// ---------------- device scratch (static: no allocations allowed) -------------
__device__ float d_W64[64 * 1024];       // (delta/N)*sig_diff[k<64][64+j], pad j<1024
__device__ float d_C[1024];              // per-column constant, padded zeros
__device__ float d_rowpart[8 * BROWS];   // per-chunk row-sum partials

// ---------------- helpers ----------------------------------------------------
static __device__ __forceinline__ float sigd(float idv, float e, float iv, float b) {
    return expf(-b * fabsf(e - idv)) - expf(-b * fabsf(iv - idv));
}
static __device__ __forceinline__ unsigned long long splat2(float x) {
    unsigned long long d;
    asm("mov.b64 %0, {%1, %1};" : "=l"(d) : "f"(x));
    return d;
}
static __device__ __forceinline__ unsigned long long ffma2(unsigned long long a,
                                                           unsigned long long b,
                                                           unsigned long long c) {
    unsigned long long d;
    asm("fma.rn.f32x2 %0, %1, %2, %3;" : "=l"(d) : "l"(a), "l"(b), "l"(c));
    return d;
}
static __device__ __forceinline__ void unpack2(unsigned long long v, float& lo, float& hi) {
    asm("mov.b64 {%0, %1}, %2;" : "=f"(lo), "=f"(hi) : "l"(v));
}
static __device__ __forceinline__ float warp_sum(float v) {
    #pragma unroll
    for (int o = 16; o; o >>= 1) v += __shfl_xor_sync(0xffffffffu, v, o);
    return v;
}
static __device__ __forceinline__ unsigned smem_u32(const void* p) {
    unsigned a;
    asm("{ .reg .u64 t; cvta.to.shared.u64 t, %1; cvt.u32.u64 %0, t; }"
        : "=r"(a) : "l"(p));
    return a;
}
static __device__ __forceinline__ void cluster_sync_hw() {
    asm volatile("barrier.cluster.arrive.aligned;" ::: "memory");
    asm volatile("barrier.cluster.wait.aligned;"   ::: "memory");
}
static __device__ __forceinline__ float dsmem_ld(unsigned local_addr, int rank) {
    unsigned rem;
    asm("mapa.shared::cluster.u32 %0, %1, %2;" : "=r"(rem) : "r"(local_addr), "r"(rank));
    float v;
    asm volatile("ld.shared::cluster.f32 %0, [%1];" : "=f"(v) : "r"(rem));
    return v;
}

// ---------------- warm smem layout (float units) ------------------------------
// w2_s: [60][448] __nv_bfloat162 (one float slot each)
#define OFF_U   (JB * TAILP)          // 26880: u_s[960]
#define OFF_H   (OFF_U + RTAIL)       // h_s[60] (+pad)
#define OFF_XB  (OFF_H + 64)          // xbuf[2][60]
#define OFF_RED (OFF_XB + 2 * JB)     // red[8]
#define WARM_FLOATS (OFF_RED + 8)
#define WARM_SMEM (WARM_FLOATS * 4)   // ~112 KB

// ---------------- kernel 1: clustered warmup (bf16 weights) ------------------
__global__ void __launch_bounds__(256, 1) __cluster_dims__(CB, 1, 1)
warm_kernel(const float* __restrict__ ids, const float* __restrict__ enh,
            const float* __restrict__ inh, const float* __restrict__ beta,
            const float* __restrict__ delta) {
    extern __shared__ float sm[];
    __nv_bfloat162* w2_s = (__nv_bfloat162*)sm;   // [60][448]
    float* u_s = sm + OFF_U;      // [960]
    float* h_s = sm + OFF_H;      // [60]
    float* xb  = sm + OFF_XB;     // [2][60]
    float* red = sm + OFF_RED;    // [8]

    const float b  = beta[0];
    const float dn = delta[0] * (1.0f / (float)NN);
    const int tid  = threadIdx.x;
    const int bid  = blockIdx.x;          // == cluster rank
    const int warp = tid >> 5;
    const int lane = tid & 31;
    const int j0   = bid * JB;

    // --- setup: W64 global fill (for gemm) -----------------------------------
    for (int idx = bid * 256 + tid; idx < 64 * 1024; idx += CB * 256) {
        int k = idx >> 10, j = idx & 1023;
        float v = 0.f;
        if (j < RTAIL) v = dn * sigd(ids[II + j], enh[k], inh[k], b);
        d_W64[idx] = v;
    }
    // --- setup: local bf16x2 weight slice, rows 128..1023 --------------------
    for (int idx = tid; idx < JB * TAILP; idx += 256) {
        int c = idx / TAILP, i2 = idx - c * TAILP;
        float idv = ids[II + j0 + c];
        int k0 = 128 + 2 * i2;
        float v0 = sigd(idv, enh[k0], inh[k0], b);
        float v1 = sigd(idv, enh[k0 + 1], inh[k0 + 1], b);
        w2_s[idx] = __floats2bfloat162_rn(v0, v1);
    }
    // --- setup: head terms h_s[c] --------------------------------------------
    for (int c = warp; c < JB; c += 8) {
        float idv = ids[II + j0 + c];
        float hv = sigd(idv, enh[lane], inh[lane], b)
                 + sigd(idv, enh[lane + 32], inh[lane + 32], b);
        hv = warp_sum(hv);
        if (lane == 0) h_s[c] = hv * (1.0f / (float)NN);
    }
    // --- setup: u = 1/N, C padding -------------------------------------------
    for (int i = tid; i < RTAIL; i += 256) u_s[i] = 1.0f / (float)NN;
    if (bid == 0 && tid < 64) d_C[RTAIL + tid] = 0.f;
    __syncthreads();

    // column ownership: warps 0-3 -> 8 cols, warps 4-7 -> 7 cols (total 60)
    const int nc = (warp < 4) ? 8 : 7;
    const int cbse = (warp < 4) ? warp * 8 : 32 + (warp - 4) * 7;
    const __nv_bfloat162* wp = &w2_s[cbse * TAILP];

    float inv = 1.0f;   // it==0: reference applies step to raw conc0
    for (int it = 0; it < NWARM; ++it) {
        const int buf = it & 1;

        // ---- dots: u pairs (LDS.64) x bf16x2 weights ------------------------
        float acc[8];
        #pragma unroll
        for (int c = 0; c < 8; ++c) acc[c] = 0.f;
        #pragma unroll 2
        for (int q = 0; q < 14; ++q) {
            const int i2 = lane + 32 * q;
            float2 u2 = *(const float2*)&u_s[64 + 2 * i2];
            #pragma unroll
            for (int c = 0; c < 8; ++c) {
                float2 w = __bfloat1622float2(wp[c * TAILP + i2]);
                acc[c] = fmaf(u2.y, w.y, fmaf(u2.x, w.x, acc[c]));
            }
        }
        #pragma unroll
        for (int c = 0; c < 8; ++c) {
            float dsum = warp_sum(acc[c]);
            if (lane == 0 && c < nc) {
                int cl = cbse + c;
                float uo = u_s[j0 + cl];
                float nv = fmaxf(uo * inv + dn * (h_s[cl] + dsum * inv), 0.f);
                xb[buf * JB + cl] = nv;
            }
        }

        // ---- cluster barrier: all new u published in peers' smem ------------
        cluster_sync_hw();

        // ---- gather full u from all 16 CTAs via DSMEM; local s reduce -------
        float p = 0.f;
        const unsigned xb_base = smem_u32(&xb[buf * JB]);
        #pragma unroll
        for (int r = 0; r < 4; ++r) {
            int i = tid + 256 * r;
            if (i < RTAIL) {
                int owner = i / JB;
                int slot  = i - owner * JB;
                float v = dsmem_ld(xb_base + slot * 4, owner);
                u_s[i] = v;
                p += v;
            }
        }
        p = warp_sum(p);
        if (lane == 0) red[warp] = p;
        __syncthreads();
        float s = red[0] + red[1] + red[2] + red[3]
                + red[4] + red[5] + red[6] + red[7];
        inv = (s > 0.f) ? 1.0f / s : 1.0f;
        // next write to red / u_s is separated by the next cluster_sync
    }

    // ---- final: C_j = u_j*inv + dn*dot(u)*inv -------------------------------
    {
        float acc[8];
        #pragma unroll
        for (int c = 0; c < 8; ++c) acc[c] = 0.f;
        #pragma unroll 2
        for (int q = 0; q < 14; ++q) {
            const int i2 = lane + 32 * q;
            float2 u2 = *(const float2*)&u_s[64 + 2 * i2];
            #pragma unroll
            for (int c = 0; c < 8; ++c) {
                float2 w = __bfloat1622float2(wp[c * TAILP + i2]);
                acc[c] = fmaf(u2.y, w.y, fmaf(u2.x, w.x, acc[c]));
            }
        }
        #pragma unroll
        for (int c = 0; c < 8; ++c) {
            float dsum = warp_sum(acc[c]);
            if (lane == 0 && c < nc) {
                int cl = cbse + c;
                d_C[j0 + cl] = u_s[j0 + cl] * inv + dn * dsum * inv;
            }
        }
    }
    cluster_sync_hw();   // no CTA exits while peers may still DSMEM-read
}

// ---------------- kernel 2: GEMM, grid = (row tiles, 8 col chunks) -----------
#define TM 128
#define AS_STRIDE 132
#define SMEM_GEMM ((64 * AS_STRIDE + 64 * AS_STRIDE) * 4)

__global__ void __launch_bounds__(256)
gemm_kernel(const float* __restrict__ inp, float* __restrict__ out) {
    extern __shared__ float sm[];
    float* As = sm;                      // [64][132]  A^T: As[k][row]
    float* Ws = As + 64 * AS_STRIDE;     // [64][132]  chunk of W64

    const int tid = threadIdx.x;
    const int tx = tid & 15, ty = tid >> 4;
    const int b0 = blockIdx.x * TM;
    const int chunk = blockIdx.y;
    const int cbase = chunk * 128;

    for (int idx = tid; idx < TM * 64; idx += 256) {
        int row = idx >> 6, k = idx & 63;
        As[k * AS_STRIDE + row] = inp[(b0 + row) * 64 + k];
    }
    for (int idx = tid; idx < 64 * 128; idx += 256) {
        int k = idx >> 7, j = idx & 127;
        Ws[k * AS_STRIDE + j] = d_W64[k * 1024 + cbase + j];
    }
    __syncthreads();

    unsigned long long acc[8][4];
    #pragma unroll
    for (int r = 0; r < 8; ++r)
        #pragma unroll
        for (int c = 0; c < 4; ++c) acc[r][c] = 0ull;

    #pragma unroll 4
    for (int k = 0; k < 64; ++k) {
        float4 a0 = *(const float4*)&As[k * AS_STRIDE + ty * 8];
        float4 a1 = *(const float4*)&As[k * AS_STRIDE + ty * 8 + 4];
        ulonglong2 w01 = *(const ulonglong2*)&Ws[k * AS_STRIDE + tx * 8];
        ulonglong2 w23 = *(const ulonglong2*)&Ws[k * AS_STRIDE + tx * 8 + 4];
        unsigned long long sp[8];
        sp[0] = splat2(a0.x); sp[1] = splat2(a0.y);
        sp[2] = splat2(a0.z); sp[3] = splat2(a0.w);
        sp[4] = splat2(a1.x); sp[5] = splat2(a1.y);
        sp[6] = splat2(a1.z); sp[7] = splat2(a1.w);
        #pragma unroll
        for (int r = 0; r < 8; ++r) {
            acc[r][0] = ffma2(sp[r], w01.x, acc[r][0]);
            acc[r][1] = ffma2(sp[r], w01.y, acc[r][1]);
            acc[r][2] = ffma2(sp[r], w23.x, acc[r][2]);
            acc[r][3] = ffma2(sp[r], w23.y, acc[r][3]);
        }
    }

    float cv[8];
    #pragma unroll
    for (int cc = 0; cc < 8; ++cc) cv[cc] = d_C[cbase + tx * 8 + cc];
    const bool store0 = (chunk == 0) && (tx < 8);

    float s_part[8];
    #pragma unroll
    for (int r = 0; r < 8; ++r) {
        int row = ty * 8 + r;
        float sp_r = 0.f;
        #pragma unroll
        for (int cp = 0; cp < 4; ++cp) {
            float lo, hi;
            unpack2(acc[r][cp], lo, hi);
            float v0 = fmaxf(cv[cp * 2] + lo, 0.f);
            float v1 = fmaxf(cv[cp * 2 + 1] + hi, 0.f);
            sp_r += v0 + v1;
            if (store0) {
                out[(b0 + row) * 64 + tx * 8 + cp * 2]     = v0;
                out[(b0 + row) * 64 + tx * 8 + cp * 2 + 1] = v1;
            }
        }
        s_part[r] = sp_r;
    }
    #pragma unroll
    for (int r = 0; r < 8; ++r) {
        #pragma unroll
        for (int m = 8; m; m >>= 1)
            s_part[r] += __shfl_xor_sync(0xffffffffu, s_part[r], m, 16);
    }
    if (tx == 0) {
        #pragma unroll
        for (int r = 0; r < 8; ++r)
            d_rowpart[chunk * BROWS + b0 + ty * 8 + r] = s_part[r];
    }
}

// ---------------- kernel 3: normalize rows (in-place on out) -----------------
__global__ void __launch_bounds__(256)
scale_kernel(float* __restrict__ out) {
    __shared__ float inv_s[256];
    const int tid = threadIdx.x;
    const int base = blockIdx.x * 256;

    float s = 0.f;
    #pragma unroll
    for (int c = 0; c < 8; ++c) s += d_rowpart[c * BROWS + base + tid];
    inv_s[tid] = (s > 0.f) ? 1.0f / s : 1.0f;
    __syncthreads();

    for (int idx = tid; idx < 256 * 64; idx += 256) {
        int r = idx >> 6;
        out[base * 64 + idx] *= inv_s[r];
    }
}

// ---------------- launch ------------------------------------------------------
extern "C" void kernel_launch(void* const* d_in, const int* in_sizes, int n_in,
                              void* d_out, int out_size) {
    const float* inputs = (const float*)d_in[0];
    const float* ids    = (const float*)d_in[1];
    const float* enh    = (const float*)d_in[2];
    const float* inh    = (const float*)d_in[3];
    const float* beta   = (const float*)d_in[4];
    const float* delta  = (const float*)d_in[5];

    cudaFuncSetAttribute(warm_kernel,
                         cudaFuncAttributeNonPortableClusterSizeAllowed, 1);
    cudaFuncSetAttribute(warm_kernel,
                         cudaFuncAttributeMaxDynamicSharedMemorySize, WARM_SMEM);
    cudaFuncSetAttribute(gemm_kernel,
                         cudaFuncAttributeMaxDynamicSharedMemorySize, SMEM_GEMM);

    warm_kernel<<<CB, 256, WARM_SMEM>>>(ids, enh, inh, beta, delta);

    dim3 grid(BROWS / TM, 8);
    gemm_kernel<<<grid, 256, SMEM_GEMM>>>(inputs, (float*)d_out);

    scale_kernel<<<BROWS / 256, 256>>>((float*)d_out);
}

// round 9
// speedup vs baseline: 1.4312x; 1.0476x over previous
#include <cuda_runtime.h>
#include <cuda_bf16.h>

// Problem constants
#define NN    1024
#define II    64
#define RTAIL 960          // N - I
#define TAILK 896          // rows 128..1023
#define TAILP 448          // TAILK/2 (bf16x2 pairs)
#define NWARM 25
#define CB    16           // warm cluster size == grid size
#define JB    60           // tail columns per warm block (16*60 = 960)
#define BROWS 16384

// ---------------- device scratch (static: no allocations allowed) -------------
__device__ float d_W64[64 * 1024];       // (delta/N)*sig_diff[k<64][64+j], pad j<1024
__device__ float d_C[1024];              // per-column constant, padded zeros
__device__ float d_rowpart[8 * BROWS];   // per-chunk row-sum partials

// ---------------- helpers ----------------------------------------------------
static __device__ __forceinline__ float sigd(float idv, float e, float iv, float b) {
    return expf(-b * fabsf(e - idv)) - expf(-b * fabsf(iv - idv));
}
static __device__ __forceinline__ unsigned long long splat2(float x) {
    unsigned long long d;
    asm("mov.b64 %0, {%1, %1};" : "=l"(d) : "f"(x));
    return d;
}
static __device__ __forceinline__ unsigned long long ffma2(unsigned long long a,
                                                           unsigned long long b,
                                                           unsigned long long c) {
    unsigned long long d;
    asm("fma.rn.f32x2 %0, %1, %2, %3;" : "=l"(d) : "l"(a), "l"(b), "l"(c));
    return d;
}
static __device__ __forceinline__ void unpack2(unsigned long long v, float& lo, float& hi) {
    asm("mov.b64 {%0, %1}, %2;" : "=f"(lo), "=f"(hi) : "l"(v));
}
static __device__ __forceinline__ float warp_sum(float v) {
    #pragma unroll
    for (int o = 16; o; o >>= 1) v += __shfl_xor_sync(0xffffffffu, v, o);
    return v;
}
static __device__ __forceinline__ unsigned smem_u32(const void* p) {
    unsigned a;
    asm("{ .reg .u64 t; cvta.to.shared.u64 t, %1; cvt.u32.u64 %0, t; }"
        : "=r"(a) : "l"(p));
    return a;
}
static __device__ __forceinline__ void cluster_sync_hw() {
    asm volatile("barrier.cluster.arrive.aligned;" ::: "memory");
    asm volatile("barrier.cluster.wait.aligned;"   ::: "memory");
}
static __device__ __forceinline__ float dsmem_ld(unsigned local_addr, int rank) {
    unsigned rem;
    asm("mapa.shared::cluster.u32 %0, %1, %2;" : "=r"(rem) : "r"(local_addr), "r"(rank));
    float v;
    asm volatile("ld.shared::cluster.f32 %0, [%1];" : "=f"(v) : "r"(rem));
    return v;
}

// ---------------- warm smem layout (float units) ------------------------------
#define OFF_U   (JB * TAILP)          // 26880: u_s[960]
#define OFF_H   (OFF_U + RTAIL)       // h_s[60] (+pad)
#define OFF_XB  (OFF_H + 64)          // xbuf[2][60]
#define OFF_RED (OFF_XB + 2 * JB)     // red[16]
#define WARM_FLOATS (OFF_RED + 16)
#define WARM_SMEM (WARM_FLOATS * 4)   // ~112 KB
#define WT 512                        // warm threads

// ---------------- kernel 1: clustered warmup (bf16 weights, 512 thr) ---------
__global__ void __launch_bounds__(WT, 1) __cluster_dims__(CB, 1, 1)
warm_kernel(const float* __restrict__ ids, const float* __restrict__ enh,
            const float* __restrict__ inh, const float* __restrict__ beta,
            const float* __restrict__ delta) {
    extern __shared__ float sm[];
    __nv_bfloat162* w2_s = (__nv_bfloat162*)sm;   // [60][448]
    float* u_s = sm + OFF_U;      // [960]
    float* h_s = sm + OFF_H;      // [60]
    float* xb  = sm + OFF_XB;     // [2][60]
    float* red = sm + OFF_RED;    // [16]

    const float b  = beta[0];
    const float dn = delta[0] * (1.0f / (float)NN);
    const int tid  = threadIdx.x;
    const int bid  = blockIdx.x;          // == cluster rank
    const int warp = tid >> 5;
    const int lane = tid & 31;
    const int j0   = bid * JB;

    // --- setup: W64 global fill (for gemm) -----------------------------------
    for (int idx = bid * WT + tid; idx < 64 * 1024; idx += CB * WT) {
        int k = idx >> 10, j = idx & 1023;
        float v = 0.f;
        if (j < RTAIL) v = dn * sigd(ids[II + j], enh[k], inh[k], b);
        d_W64[idx] = v;
    }
    // --- setup: local bf16x2 weight slice, rows 128..1023 --------------------
    for (int idx = tid; idx < JB * TAILP; idx += WT) {
        int c = idx / TAILP, i2 = idx - c * TAILP;
        float idv = ids[II + j0 + c];
        int k0 = 128 + 2 * i2;
        float v0 = sigd(idv, enh[k0], inh[k0], b);
        float v1 = sigd(idv, enh[k0 + 1], inh[k0 + 1], b);
        w2_s[idx] = __floats2bfloat162_rn(v0, v1);
    }
    // --- setup: head terms h_s[c] --------------------------------------------
    for (int c = warp; c < JB; c += 16) {
        float idv = ids[II + j0 + c];
        float hv = sigd(idv, enh[lane], inh[lane], b)
                 + sigd(idv, enh[lane + 32], inh[lane + 32], b);
        hv = warp_sum(hv);
        if (lane == 0) h_s[c] = hv * (1.0f / (float)NN);
    }
    // --- setup: u = 1/N, C padding -------------------------------------------
    for (int i = tid; i < RTAIL; i += WT) u_s[i] = 1.0f / (float)NN;
    if (bid == 0 && tid < 64) d_C[RTAIL + tid] = 0.f;
    __syncthreads();

    // column ownership: warps 0-14 -> 4 cols each (60), warp 15 -> none
    const int nc = (warp < 15) ? 4 : 0;
    const int cbse = warp * 4;
    const __nv_bfloat162* wp = &w2_s[cbse * TAILP];

    float inv = 1.0f;   // it==0: reference applies step to raw conc0
    for (int it = 0; it < NWARM; ++it) {
        const int buf = it & 1;

        // ---- dots: u pairs (LDS.64) x bf16x2 weights ------------------------
        float acc[4];
        #pragma unroll
        for (int c = 0; c < 4; ++c) acc[c] = 0.f;
        if (nc) {
            #pragma unroll 2
            for (int q = 0; q < 14; ++q) {
                const int i2 = lane + 32 * q;
                float2 u2 = *(const float2*)&u_s[64 + 2 * i2];
                #pragma unroll
                for (int c = 0; c < 4; ++c) {
                    float2 w = __bfloat1622float2(wp[c * TAILP + i2]);
                    acc[c] = fmaf(u2.y, w.y, fmaf(u2.x, w.x, acc[c]));
                }
            }
            #pragma unroll
            for (int c = 0; c < 4; ++c) {
                float dsum = warp_sum(acc[c]);
                if (lane == 0) {
                    int cl = cbse + c;
                    float uo = u_s[j0 + cl];
                    float nv = fmaxf(uo * inv + dn * (h_s[cl] + dsum * inv), 0.f);
                    xb[buf * JB + cl] = nv;
                }
            }
        }

        // ---- cluster barrier: all new u published in peers' smem ------------
        cluster_sync_hw();

        // ---- gather full u from all 16 CTAs via DSMEM; local s reduce -------
        float p = 0.f;
        const unsigned xb_base = smem_u32(&xb[buf * JB]);
        #pragma unroll
        for (int r = 0; r < 2; ++r) {
            int i = tid + WT * r;
            if (i < RTAIL) {
                int owner = i / JB;
                int slot  = i - owner * JB;
                float v = dsmem_ld(xb_base + slot * 4, owner);
                u_s[i] = v;
                p += v;
            }
        }
        p = warp_sum(p);
        if (lane == 0) red[warp] = p;
        __syncthreads();
        float sv = (lane < 16) ? red[lane] : 0.f;
        float s = warp_sum(sv);
        inv = (s > 0.f) ? 1.0f / s : 1.0f;
    }

    // ---- final: C_j = u_j*inv + dn*dot(u)*inv -------------------------------
    if (nc) {
        float acc[4];
        #pragma unroll
        for (int c = 0; c < 4; ++c) acc[c] = 0.f;
        #pragma unroll 2
        for (int q = 0; q < 14; ++q) {
            const int i2 = lane + 32 * q;
            float2 u2 = *(const float2*)&u_s[64 + 2 * i2];
            #pragma unroll
            for (int c = 0; c < 4; ++c) {
                float2 w = __bfloat1622float2(wp[c * TAILP + i2]);
                acc[c] = fmaf(u2.y, w.y, fmaf(u2.x, w.x, acc[c]));
            }
        }
        #pragma unroll
        for (int c = 0; c < 4; ++c) {
            float dsum = warp_sum(acc[c]);
            if (lane == 0) {
                int cl = cbse + c;
                d_C[j0 + cl] = u_s[j0 + cl] * inv + dn * dsum * inv;
            }
        }
    }
    cluster_sync_hw();   // no CTA exits while peers may still DSMEM-read
}

// ---------------- kernel 2: GEMM, grid = (row tiles, 8 col chunks) -----------
// Warp lane shape 8 tx x 4 ty -> per-warp LDS traffic 384B/k (was 1088B/k).
#define TM 128
#define AS_STRIDE 132
#define SMEM_GEMM ((64 * AS_STRIDE + 64 * AS_STRIDE + 256) * 4)

__global__ void __launch_bounds__(256)
gemm_kernel(const float* __restrict__ inp, float* __restrict__ out) {
    extern __shared__ float sm[];
    float* As = sm;                      // [64][132]  A^T: As[k][row]
    float* Ws = As + 64 * AS_STRIDE;     // [64][132]  chunk of W64
    float* rs = Ws + 64 * AS_STRIDE;     // [128][2]   row-sum halves

    const int tid  = threadIdx.x;
    const int lane = tid & 31;
    const int wid  = tid >> 5;
    const int tx = (lane & 7) | ((wid & 1) << 3);   // 0..15
    const int ty = (lane >> 3) | ((wid >> 1) << 2); // 0..15
    const int b0 = blockIdx.x * TM;
    const int chunk = blockIdx.y;
    const int cbase = chunk * 128;

    for (int idx = tid; idx < TM * 64; idx += 256) {
        int row = idx >> 6, k = idx & 63;
        As[k * AS_STRIDE + row] = inp[(b0 + row) * 64 + k];
    }
    for (int idx = tid; idx < 64 * 128; idx += 256) {
        int k = idx >> 7, j = idx & 127;
        Ws[k * AS_STRIDE + j] = d_W64[k * 1024 + cbase + j];
    }
    __syncthreads();

    unsigned long long acc[8][4];
    #pragma unroll
    for (int r = 0; r < 8; ++r)
        #pragma unroll
        for (int c = 0; c < 4; ++c) acc[r][c] = 0ull;

    #pragma unroll 4
    for (int k = 0; k < 64; ++k) {
        float4 a0 = *(const float4*)&As[k * AS_STRIDE + ty * 8];
        float4 a1 = *(const float4*)&As[k * AS_STRIDE + ty * 8 + 4];
        ulonglong2 w01 = *(const ulonglong2*)&Ws[k * AS_STRIDE + tx * 8];
        ulonglong2 w23 = *(const ulonglong2*)&Ws[k * AS_STRIDE + tx * 8 + 4];
        unsigned long long sp[8];
        sp[0] = splat2(a0.x); sp[1] = splat2(a0.y);
        sp[2] = splat2(a0.z); sp[3] = splat2(a0.w);
        sp[4] = splat2(a1.x); sp[5] = splat2(a1.y);
        sp[6] = splat2(a1.z); sp[7] = splat2(a1.w);
        #pragma unroll
        for (int r = 0; r < 8; ++r) {
            acc[r][0] = ffma2(sp[r], w01.x, acc[r][0]);
            acc[r][1] = ffma2(sp[r], w01.y, acc[r][1]);
            acc[r][2] = ffma2(sp[r], w23.x, acc[r][2]);
            acc[r][3] = ffma2(sp[r], w23.y, acc[r][3]);
        }
    }

    float cv[8];
    #pragma unroll
    for (int cc = 0; cc < 8; ++cc) cv[cc] = d_C[cbase + tx * 8 + cc];
    const bool store0 = (chunk == 0) && (tx < 8);

    float s_part[8];
    #pragma unroll
    for (int r = 0; r < 8; ++r) {
        int row = ty * 8 + r;
        float sp_r = 0.f;
        #pragma unroll
        for (int cp = 0; cp < 4; ++cp) {
            float lo, hi;
            unpack2(acc[r][cp], lo, hi);
            float v0 = fmaxf(cv[cp * 2] + lo, 0.f);
            float v1 = fmaxf(cv[cp * 2 + 1] + hi, 0.f);
            sp_r += v0 + v1;
            if (store0) {
                out[(b0 + row) * 64 + tx * 8 + cp * 2]     = v0;
                out[(b0 + row) * 64 + tx * 8 + cp * 2 + 1] = v1;
            }
        }
        s_part[r] = sp_r;
    }
    // reduce over the 8 tx-low lanes (lane bits 0..2)
    #pragma unroll
    for (int r = 0; r < 8; ++r) {
        #pragma unroll
        for (int m = 1; m < 8; m <<= 1)
            s_part[r] += __shfl_xor_sync(0xffffffffu, s_part[r], m);
    }
    if ((lane & 7) == 0) {
        #pragma unroll
        for (int r = 0; r < 8; ++r)
            rs[(ty * 8 + r) * 2 + (wid & 1)] = s_part[r];
    }
    __syncthreads();
    if (tid < TM)
        d_rowpart[chunk * BROWS + b0 + tid] = rs[tid * 2] + rs[tid * 2 + 1];
}

// ---------------- kernel 3: normalize rows (in-place on out) -----------------
__global__ void __launch_bounds__(256)
scale_kernel(float* __restrict__ out) {
    __shared__ float inv_s[256];
    const int tid = threadIdx.x;
    const int base = blockIdx.x * 256;

    float s = 0.f;
    #pragma unroll
    for (int c = 0; c < 8; ++c) s += d_rowpart[c * BROWS + base + tid];
    inv_s[tid] = (s > 0.f) ? 1.0f / s : 1.0f;
    __syncthreads();

    for (int idx = tid; idx < 256 * 64; idx += 256) {
        int r = idx >> 6;
        out[base * 64 + idx] *= inv_s[r];
    }
}

// ---------------- launch ------------------------------------------------------
extern "C" void kernel_launch(void* const* d_in, const int* in_sizes, int n_in,
                              void* d_out, int out_size) {
    const float* inputs = (const float*)d_in[0];
    const float* ids    = (const float*)d_in[1];
    const float* enh    = (const float*)d_in[2];
    const float* inh    = (const float*)d_in[3];
    const float* beta   = (const float*)d_in[4];
    const float* delta  = (const float*)d_in[5];

    cudaFuncSetAttribute(warm_kernel,
                         cudaFuncAttributeNonPortableClusterSizeAllowed, 1);
    cudaFuncSetAttribute(warm_kernel,
                         cudaFuncAttributeMaxDynamicSharedMemorySize, WARM_SMEM);
    cudaFuncSetAttribute(gemm_kernel,
                         cudaFuncAttributeMaxDynamicSharedMemorySize, SMEM_GEMM);

    warm_kernel<<<CB, WT, WARM_SMEM>>>(ids, enh, inh, beta, delta);

    dim3 grid(BROWS / TM, 8);
    gemm_kernel<<<grid, 256, SMEM_GEMM>>>(inputs, (float*)d_out);

    scale_kernel<<<BROWS / 256, 256>>>((float*)d_out);
}